// round 1
// baseline (speedup 1.0000x reference)
#include <cuda_runtime.h>
#include <cstdint>

#define BB 32
#define NN 512
#define FF 64
#define HH 8
#define ROWS (BB*NN)   // 16384

// ---------------- scratch (static device globals; no allocation) ----------------
__device__ __align__(16) int16_t g_nbr[ROWS * NN];      // 16 MB neighbor lists
__device__              int      g_cnt[ROWS];
__device__ __align__(16) float   g_hp0[ROWS * FF];      // 4 MB
__device__ __align__(16) float   g_s0[BB*HH*NN], g_d0[BB*HH*NN];
__device__ __align__(16) float   g_x1[ROWS * (HH*FF)];  // 32 MB (elu'd concat)
__device__ __align__(16) float   g_hp1[ROWS * FF];
__device__ __align__(16) float   g_s1[BB*HH*NN], g_d1[BB*HH*NN];

// ---------------- packed f32x2 helpers (FFMA2: 2x fp32 FMA throughput) ----------
static __device__ __forceinline__ unsigned long long fma2(unsigned long long a,
                                                          unsigned long long b,
                                                          unsigned long long c) {
    unsigned long long r;
    asm("fma.rn.f32x2 %0, %1, %2, %3;" : "=l"(r) : "l"(a), "l"(b), "l"(c));
    return r;
}
static __device__ __forceinline__ unsigned long long pk2(float x, float y) {
    unsigned long long r;
    asm("mov.b64 %0, {%1, %2};" : "=l"(r) : "f"(x), "f"(y));
    return r;
}
static __device__ __forceinline__ void upk2(unsigned long long v, float& x, float& y) {
    asm("mov.b64 {%0, %1}, %2;" : "=f"(x), "=f"(y) : "l"(v));
}

// ---------------- kernel 1: compact adjacency rows into neighbor lists ----------
__global__ void __launch_bounds__(256) k_build_nbr(const float* __restrict__ adj) {
    const int row  = (blockIdx.x << 3) + (threadIdx.x >> 5);
    const int lane = threadIdx.x & 31;
    const int i    = row & (NN - 1);
    const float* arow = adj + ((size_t)row << 9);
    int16_t* outp = g_nbr + ((size_t)row << 9);
    int off = 0;
    #pragma unroll
    for (int base = 0; base < NN; base += 32) {
        const int j = base + lane;
        const bool p = (arow[j] != 0.f) || (j == i);   // diag forced to 1
        const unsigned msk = __ballot_sync(0xffffffffu, p);
        if (p) outp[off + __popc(msk & ((1u << lane) - 1u))] = (int16_t)j;
        off += __popc(msk);
    }
    if (lane == 0) g_cnt[row] = off;
}

// ---------------- kernel 2: GEMM  C[M,64] = A[M,K] @ B[K,64]  -------------------
// BM=64,BN=64,BK=32, 256 thr, 4x4 micro-tile with f32x2 accumulators.
template<int K, int LAYER>
__global__ void __launch_bounds__(256) k_gemm(const float* __restrict__ Aext,
                                              const float* __restrict__ Bw) {
    const float* __restrict__ A = (LAYER == 0) ? Aext : g_x1;
    float* __restrict__ C = (LAYER == 0) ? g_hp0 : g_hp1;
    __shared__ float As[32][72];   // As[kk][m] (transposed)
    __shared__ float Bs[32][72];   // Bs[kk][n]
    const int bm = blockIdx.x << 6;
    const int t  = threadIdx.x;
    const int ty = t >> 4, tx = t & 15;
    unsigned long long acc[4][2];
    #pragma unroll
    for (int r = 0; r < 4; r++) { acc[r][0] = 0ull; acc[r][1] = 0ull; }

    for (int k0 = 0; k0 < K; k0 += 32) {
        #pragma unroll
        for (int l = 0; l < 2; l++) {
            const int idx = t + (l << 8);          // 0..511
            const int m  = idx >> 3;
            const int kq = (idx & 7) << 2;
            float4 av = *(const float4*)(A + (size_t)(bm + m) * K + k0 + kq);
            As[kq + 0][m] = av.x; As[kq + 1][m] = av.y;
            As[kq + 2][m] = av.z; As[kq + 3][m] = av.w;
            const int kk = idx >> 4;
            const int nq = (idx & 15) << 2;
            *(float4*)&Bs[kk][nq] = *(const float4*)(Bw + (size_t)(k0 + kk) * 64 + nq);
        }
        __syncthreads();
        #pragma unroll
        for (int kk = 0; kk < 32; kk++) {
            const float4 a = *(const float4*)&As[kk][ty << 2];
            const longlong2 bv = *(const longlong2*)&Bs[kk][tx << 2];
            const unsigned long long b0 = (unsigned long long)bv.x;
            const unsigned long long b1 = (unsigned long long)bv.y;
            const unsigned long long a0 = pk2(a.x, a.x), a1 = pk2(a.y, a.y);
            const unsigned long long a2 = pk2(a.z, a.z), a3 = pk2(a.w, a.w);
            acc[0][0] = fma2(a0, b0, acc[0][0]); acc[0][1] = fma2(a0, b1, acc[0][1]);
            acc[1][0] = fma2(a1, b0, acc[1][0]); acc[1][1] = fma2(a1, b1, acc[1][1]);
            acc[2][0] = fma2(a2, b0, acc[2][0]); acc[2][1] = fma2(a2, b1, acc[2][1]);
            acc[3][0] = fma2(a3, b0, acc[3][0]); acc[3][1] = fma2(a3, b1, acc[3][1]);
        }
        __syncthreads();
    }
    #pragma unroll
    for (int r = 0; r < 4; r++) {
        float o0, o1, o2, o3;
        upk2(acc[r][0], o0, o1); upk2(acc[r][1], o2, o3);
        *(float4*)(C + (size_t)(bm + (ty << 2) + r) * 64 + (tx << 2)) =
            make_float4(o0, o1, o2, o3);
    }
}

// ---------------- kernel 3: s/d projections  s[b,h,i] = hp[b,i,:]·a_src[:,h] ----
template<int LAYER>
__global__ void __launch_bounds__(256) k_sd(const float* __restrict__ asrc,
                                            const float* __restrict__ adst) {
    const float* __restrict__ hp = (LAYER == 0) ? g_hp0 : g_hp1;
    float* __restrict__ s = (LAYER == 0) ? g_s0 : g_s1;
    float* __restrict__ d = (LAYER == 0) ? g_d0 : g_d1;
    const int row  = (blockIdx.x << 3) + (threadIdx.x >> 5);
    const int lane = threadIdx.x & 31;
    const int b = row >> 9, i = row & (NN - 1);
    const float h0 = hp[(size_t)row * 64 + lane];
    const float h1 = hp[(size_t)row * 64 + 32 + lane];
    float ps[8], pd[8];
    #pragma unroll
    for (int h = 0; h < 8; h++) {
        ps[h] = h0 * asrc[(lane << 3) + h] + h1 * asrc[((lane + 32) << 3) + h];
        pd[h] = h0 * adst[(lane << 3) + h] + h1 * adst[((lane + 32) << 3) + h];
    }
    #pragma unroll
    for (int h = 0; h < 8; h++) {
        #pragma unroll
        for (int o = 16; o; o >>= 1) {
            ps[h] += __shfl_xor_sync(0xffffffffu, ps[h], o);
            pd[h] += __shfl_xor_sync(0xffffffffu, pd[h], o);
        }
    }
    if (lane == 0) {
        #pragma unroll
        for (int h = 0; h < 8; h++) {
            s[(b << 12) + (h << 9) + i] = ps[h];
            d[(b << 12) + (h << 9) + i] = pd[h];
        }
    }
}

// ---------------- kernel 4: layer-1 sparse softmax + 8-head aggregate + elu -----
// one warp per (b,i) row; lane owns f={2l,2l+1} for all 8 heads (16 fp32 accs).
__global__ void __launch_bounds__(128) k_agg1() {
    __shared__ float2 s_w[4][64][8];          // per-warp chunk weights, pre-dup {w,w}
    __shared__ int    s_j[4][64];
    __shared__ float  s_hs[4][8], s_hm[4][8], s_hr[4][8];
    const int w = threadIdx.x >> 5, lane = threadIdx.x & 31;
    const int row = (blockIdx.x << 2) + w;
    const int b = row >> 9, i = row & (NN - 1);
    const int cnt = g_cnt[row];
    const int16_t* __restrict__ nbrrow = g_nbr + ((size_t)row << 9);
    const float* __restrict__ d0b  = g_d0  + (b << 12);
    const float* __restrict__ hp0b = g_hp0 + ((size_t)b << 15);

    float sh[8], m[8], Z[8];
    #pragma unroll
    for (int h = 0; h < 8; h++) {
        sh[h] = g_s0[(b << 12) + (h << 9) + i];
        m[h]  = -3.402823466e38f;
        Z[h]  = 0.f;
    }
    // pass A: per-head max over valid neighbors
    for (int p = lane; p < cnt; p += 32) {
        const int j = (int)nbrrow[p];
        #pragma unroll
        for (int h = 0; h < 8; h++) {
            const float ev = sh[h] + d0b[(h << 9) + j];
            const float lv = ev >= 0.f ? ev : 0.2f * ev;
            if (lv != 0.f) m[h] = fmaxf(m[h], lv);
        }
    }
    #pragma unroll
    for (int h = 0; h < 8; h++)
        #pragma unroll
        for (int o = 16; o; o >>= 1)
            m[h] = fmaxf(m[h], __shfl_xor_sync(0xffffffffu, m[h], o));
    // pass B: per-head normalizer
    for (int p = lane; p < cnt; p += 32) {
        const int j = (int)nbrrow[p];
        #pragma unroll
        for (int h = 0; h < 8; h++) {
            const float ev = sh[h] + d0b[(h << 9) + j];
            const float lv = ev >= 0.f ? ev : 0.2f * ev;
            if (lv != 0.f) Z[h] += __expf(lv - m[h]);
        }
    }
    #pragma unroll
    for (int h = 0; h < 8; h++)
        #pragma unroll
        for (int o = 16; o; o >>= 1)
            Z[h] += __shfl_xor_sync(0xffffffffu, Z[h], o);
    #pragma unroll
    for (int h = 0; h < 8; h++) {
        const float rz = 1.f / Z[h];
        if (lane == h) { s_hs[w][h] = sh[h]; s_hm[w][h] = m[h]; s_hr[w][h] = rz; }
    }
    __syncwarp();

    unsigned long long acc[8];
    #pragma unroll
    for (int h = 0; h < 8; h++) acc[h] = 0ull;

    for (int base = 0; base < cnt; base += 64) {
        const int nchunk = min(64, cnt - base);
        const int tot = nchunk << 3;
        for (int e = lane; e < tot; e += 32) {
            const int p = e >> 3, h = e & 7;
            const int j = (int)nbrrow[base + p];
            const float ev = s_hs[w][h] + d0b[(h << 9) + j];
            const float lv = ev >= 0.f ? ev : 0.2f * ev;
            const float wt = (lv != 0.f) ? __expf(lv - s_hm[w][h]) * s_hr[w][h] : 0.f;
            s_w[w][p][h] = make_float2(wt, wt);
            if (h == 0) s_j[w][p] = j;
        }
        __syncwarp();
        #pragma unroll 2
        for (int q = 0; q < nchunk; q++) {
            const int j = s_j[w][q];
            const unsigned long long hpv =
                ((const unsigned long long*)(hp0b + ((size_t)j << 6)))[lane];
            const longlong2* wp = (const longlong2*)&s_w[w][q][0];
            const longlong2 w01 = wp[0], w23 = wp[1], w45 = wp[2], w67 = wp[3];
            acc[0] = fma2((unsigned long long)w01.x, hpv, acc[0]);
            acc[1] = fma2((unsigned long long)w01.y, hpv, acc[1]);
            acc[2] = fma2((unsigned long long)w23.x, hpv, acc[2]);
            acc[3] = fma2((unsigned long long)w23.y, hpv, acc[3]);
            acc[4] = fma2((unsigned long long)w45.x, hpv, acc[4]);
            acc[5] = fma2((unsigned long long)w45.y, hpv, acc[5]);
            acc[6] = fma2((unsigned long long)w67.x, hpv, acc[6]);
            acc[7] = fma2((unsigned long long)w67.y, hpv, acc[7]);
        }
        __syncwarp();
    }
    // write x1 = elu(concat heads)
    float* xout = g_x1 + ((size_t)row << 9);
    #pragma unroll
    for (int h = 0; h < 8; h++) {
        float xf, yf; upk2(acc[h], xf, yf);
        xf = xf > 0.f ? xf : expm1f(xf);
        yf = yf > 0.f ? yf : expm1f(yf);
        ((float2*)(xout + (h << 6)))[lane] = make_float2(xf, yf);
    }
}

// ---------------- kernel 5: layer-2 aggregate with head-mean folded into weights -
__global__ void __launch_bounds__(128) k_agg2(float* __restrict__ out) {
    __shared__ float2 s_wb[4][64];
    __shared__ int    s_j[4][64];
    const int w = threadIdx.x >> 5, lane = threadIdx.x & 31;
    const int row = (blockIdx.x << 2) + w;
    const int b = row >> 9, i = row & (NN - 1);
    const int cnt = g_cnt[row];
    const int16_t* __restrict__ nbrrow = g_nbr + ((size_t)row << 9);
    const float* __restrict__ d1b  = g_d1  + (b << 12);
    const float* __restrict__ hp1b = g_hp1 + ((size_t)b << 15);

    float sh[8], m[8], Z[8];
    #pragma unroll
    for (int h = 0; h < 8; h++) {
        sh[h] = g_s1[(b << 12) + (h << 9) + i];
        m[h]  = -3.402823466e38f;
        Z[h]  = 0.f;
    }
    for (int p = lane; p < cnt; p += 32) {
        const int j = (int)nbrrow[p];
        #pragma unroll
        for (int h = 0; h < 8; h++) {
            const float ev = sh[h] + d1b[(h << 9) + j];
            const float lv = ev >= 0.f ? ev : 0.2f * ev;
            if (lv != 0.f) m[h] = fmaxf(m[h], lv);
        }
    }
    #pragma unroll
    for (int h = 0; h < 8; h++)
        #pragma unroll
        for (int o = 16; o; o >>= 1)
            m[h] = fmaxf(m[h], __shfl_xor_sync(0xffffffffu, m[h], o));
    for (int p = lane; p < cnt; p += 32) {
        const int j = (int)nbrrow[p];
        #pragma unroll
        for (int h = 0; h < 8; h++) {
            const float ev = sh[h] + d1b[(h << 9) + j];
            const float lv = ev >= 0.f ? ev : 0.2f * ev;
            if (lv != 0.f) Z[h] += __expf(lv - m[h]);
        }
    }
    #pragma unroll
    for (int h = 0; h < 8; h++)
        #pragma unroll
        for (int o = 16; o; o >>= 1)
            Z[h] += __shfl_xor_sync(0xffffffffu, Z[h], o);
    float rz[8];
    #pragma unroll
    for (int h = 0; h < 8; h++) rz[h] = 1.f / Z[h];

    unsigned long long acc = 0ull;
    for (int base = 0; base < cnt; base += 64) {
        const int nchunk = min(64, cnt - base);
        for (int p = lane; p < nchunk; p += 32) {
            const int j = (int)nbrrow[base + p];
            float ws = 0.f;
            #pragma unroll
            for (int h = 0; h < 8; h++) {
                const float ev = sh[h] + d1b[(h << 9) + j];
                const float lv = ev >= 0.f ? ev : 0.2f * ev;
                if (lv != 0.f) ws += __expf(lv - m[h]) * rz[h];
            }
            ws *= 0.125f;                       // mean over heads
            s_wb[w][p] = make_float2(ws, ws);
            s_j[w][p]  = j;
        }
        __syncwarp();
        #pragma unroll 2
        for (int q = 0; q < nchunk; q++) {
            const int j = s_j[w][q];
            const unsigned long long hpv =
                ((const unsigned long long*)(hp1b + ((size_t)j << 6)))[lane];
            const unsigned long long wv = *(const unsigned long long*)&s_wb[w][q];
            acc = fma2(wv, hpv, acc);
        }
        __syncwarp();
    }
    float xf, yf; upk2(acc, xf, yf);
    ((float2*)(out + ((size_t)row << 6)))[lane] = make_float2(xf, yf);
}

// ---------------- launch --------------------------------------------------------
extern "C" void kernel_launch(void* const* d_in, const int* in_sizes, int n_in,
                              void* d_out, int out_size) {
    const float* x     = (const float*)d_in[0];
    const float* adj   = (const float*)d_in[1];
    const float* W0    = (const float*)d_in[4];
    const float* asrc0 = (const float*)d_in[5];
    const float* adst0 = (const float*)d_in[6];
    const float* W1    = (const float*)d_in[7];
    const float* asrc1 = (const float*)d_in[8];
    const float* adst1 = (const float*)d_in[9];
    float* out = (float*)d_out;

    k_build_nbr<<<ROWS / 8, 256>>>(adj);
    k_gemm<64, 0><<<ROWS / 64, 256>>>(x, W0);
    k_sd<0><<<ROWS / 8, 256>>>(asrc0, adst0);
    k_agg1<<<ROWS / 4, 128>>>();
    k_gemm<512, 1><<<ROWS / 64, 256>>>(nullptr, W1);
    k_sd<1><<<ROWS / 8, 256>>>(asrc1, adst1);
    k_agg2<<<ROWS / 4, 128>>>(out);
}